// round 11
// baseline (speedup 1.0000x reference)
#include <cuda_runtime.h>
#include <cuda_fp16.h>
#include <cstdint>
#include <math.h>

#define Hd 512
#define Bd 4
#define Td 512
#define Ud 128
#define Vd 41
#define NTILES (Bd * Td)
#define NQUADS (NTILES / 4)
#define GRID 148

// ---------------- scratch ----------------
__device__ __align__(256) __half g_tlnh[Bd * Ud * Hd];       // LN target fp16, [b][kc(32)][u(128)][perm16]
__device__ __align__(256) uint32_t g_Bfrag[3 * 32 * 32 * 4]; // Wl fp16 B-frags [part(3)][kc][lane][w4]
__device__ unsigned int g_bar = 0;                           // monotonic grid barrier counter

// ---------------- helpers ----------------
__device__ __forceinline__ uint32_t smem_u32(const void* p) {
    uint32_t a;
    asm("{ .reg .u64 t; cvta.to.shared.u64 t, %1; cvt.u32.u64 %0, t; }" : "=r"(a) : "l"(p));
    return a;
}
__device__ __forceinline__ uint32_t f2h(float x, float y) {
    __half2 h = __floats2half2_rn(x, y);
    return *reinterpret_cast<uint32_t*>(&h);
}
__device__ __forceinline__ uint32_t hadd2u(uint32_t a, uint32_t b) {
    uint32_t d;
    asm("add.f16x2 %0, %1, %2;" : "=r"(d) : "r"(a), "r"(b));
    return d;
}
__device__ __forceinline__ uint32_t tanh2(uint32_t x) {
    asm("tanh.approx.f16x2 %0, %0;" : "+r"(x));
    return x;
}
__device__ __forceinline__ void mma16816(float* c, uint32_t a0, uint32_t a1, uint32_t a2, uint32_t a3,
                                         uint32_t b0, uint32_t b1) {
    asm volatile(
        "mma.sync.aligned.m16n8k16.row.col.f32.f16.f16.f32 "
        "{%0,%1,%2,%3}, {%4,%5,%6,%7}, {%8,%9}, {%0,%1,%2,%3};"
        : "+f"(c[0]), "+f"(c[1]), "+f"(c[2]), "+f"(c[3])
        : "r"(a0), "r"(a1), "r"(a2), "r"(a3), "r"(b0), "r"(b1));
}
__device__ __forceinline__ unsigned long long pack2(float x, float y) {
    unsigned long long r; asm("mov.b64 %0, {%1, %2};" : "=l"(r) : "f"(x), "f"(y)); return r;
}
__device__ __forceinline__ void unpack2(unsigned long long v, float& x, float& y) {
    asm("mov.b64 {%0, %1}, %2;" : "=f"(x), "=f"(y) : "l"(v));
}
__device__ __forceinline__ unsigned long long fma2(unsigned long long a, unsigned long long b, unsigned long long c) {
    unsigned long long d; asm("fma.rn.f32x2 %0, %1, %2, %3;" : "=l"(d) : "l"(a), "l"(b), "l"(c)); return d;
}

// replay-safe all-resident grid barrier (monotonic counter, no reset)
__device__ __forceinline__ void grid_barrier() {
    __syncthreads();
    if (threadIdx.x == 0) {
        __threadfence();
        unsigned nb = gridDim.x;
        unsigned t = atomicAdd(&g_bar, 1u);
        unsigned target = (t / nb + 1u) * nb;
        unsigned v;
        do {
            asm volatile("ld.acquire.gpu.global.u32 %0, [%1];" : "=r"(v) : "l"(&g_bar));
        } while (v < target);
    }
    __syncthreads();
}

// ---------------- smem layout (phase 1) ----------------
#define SM_BS   0          // 48KB B frags (3 conflict-free 16KB arrays)
#define SM_TLN  49152      // 3 x 16KB tln chunk buffers; reused as 42KB epilogue stage
#define SM_SRCP 98304      // 2 par x 128 x 2 uint4 = 8KB
#define SM_BLS  106496     // 192B padded bias
#define SM_TOT  106752

// =====================================================================
// ONE persistent kernel: phase0 (target path + B prep) -> barrier -> quad fused
// =====================================================================
__global__ __launch_bounds__(256)
void k_all(const float* __restrict__ src, const float* __restrict__ tgt,
           const float* __restrict__ W1, const float* __restrict__ b1,
           const float* __restrict__ W2, const float* __restrict__ b2,
           const float* __restrict__ lng, const float* __restrict__ lnb,
           const float* __restrict__ Wl, const float* __restrict__ bl,
           float* __restrict__ out,
           const int* __restrict__ slen, const int* __restrict__ tlen,
           long long tailbase, int tailcnt) {
    extern __shared__ __align__(16) char sm[];
    const int tid = threadIdx.x, w = tid >> 5, lane = tid & 31;
    const int gid = lane >> 2, tig = lane & 3;

    // ============== PHASE 0 ==============
    if (blockIdx.x < 128) {
        // ---- full target path, 4 rows per block ----
        unsigned long long (*As2)[Hd] = (unsigned long long(*)[Hd])sm;   // 16KB
        float (*redS)[8] = (float(*)[8])(sm + 16384);
        float (*redQ)[8] = (float(*)[8])(sm + 16384 + 128);
        float* mu_s = (float*)(sm + 16384 + 256);
        float* rs_s = mu_s + 4;

        const int m0 = blockIdx.x * 4;
        for (int i = tid; i < 4 * Hd; i += 256) {
            float v = tgt[m0 * Hd + i];
            ((unsigned long long*)As2)[i] = pack2(v, v);
        }
        __syncthreads();

        const int j0 = tid * 2;
        // GEMM1 + GELU
        unsigned long long acc[4];
        {
            unsigned long long bb = pack2(b1[j0], b1[j0 + 1]);
#pragma unroll
            for (int r = 0; r < 4; r++) acc[r] = bb;
        }
        for (int k = 0; k < Hd; k += 4) {
            unsigned long long wv[4];
#pragma unroll
            for (int q = 0; q < 4; q++) {
                float2 t2 = *(const float2*)(W1 + (k + q) * Hd + j0);
                wv[q] = pack2(t2.x, t2.y);
            }
#pragma unroll
            for (int q = 0; q < 4; q++)
#pragma unroll
                for (int r = 0; r < 4; r++) acc[r] = fma2(As2[r][k + q], wv[q], acc[r]);
        }
        float gxs[4], gys[4];
#pragma unroll
        for (int r = 0; r < 4; r++) {
            float x, y; unpack2(acc[r], x, y);
            gxs[r] = 0.5f * x * (1.0f + erff(x * 0.7071067811865475f));
            gys[r] = 0.5f * y * (1.0f + erff(y * 0.7071067811865475f));
        }
        __syncthreads();          // all As2 reads done
#pragma unroll
        for (int r = 0; r < 4; r++) {
            As2[r][j0] = pack2(gxs[r], gxs[r]);
            As2[r][j0 + 1] = pack2(gys[r], gys[r]);
        }
        __syncthreads();

        // GEMM2 + LN
        {
            unsigned long long bb = pack2(b2[j0], b2[j0 + 1]);
#pragma unroll
            for (int r = 0; r < 4; r++) acc[r] = bb;
        }
        for (int k = 0; k < Hd; k += 4) {
            unsigned long long wv[4];
#pragma unroll
            for (int q = 0; q < 4; q++) {
                float2 t2 = *(const float2*)(W2 + (k + q) * Hd + j0);
                wv[q] = pack2(t2.x, t2.y);
            }
#pragma unroll
            for (int q = 0; q < 4; q++)
#pragma unroll
                for (int r = 0; r < 4; r++) acc[r] = fma2(As2[r][k + q], wv[q], acc[r]);
        }
        float xs[4], ys[4];
#pragma unroll
        for (int r = 0; r < 4; r++) unpack2(acc[r], xs[r], ys[r]);

#pragma unroll
        for (int r = 0; r < 4; r++) {
            float s = xs[r] + ys[r];
            float q = xs[r] * xs[r] + ys[r] * ys[r];
#pragma unroll
            for (int off = 16; off > 0; off >>= 1) {
                s += __shfl_down_sync(0xFFFFFFFFu, s, off);
                q += __shfl_down_sync(0xFFFFFFFFu, q, off);
            }
            if (lane == 0) { redS[r][w] = s; redQ[r][w] = q; }
        }
        __syncthreads();
        if (tid < 4) {
            float s = 0.f, q = 0.f;
#pragma unroll
            for (int j = 0; j < 8; j++) { s += redS[tid][j]; q += redQ[tid][j]; }
            float mu = s * (1.0f / Hd);
            float var = q * (1.0f / Hd) - mu * mu;
            mu_s[tid] = mu;
            rs_s[tid] = rsqrtf(var + 1e-5f);
        }
        __syncthreads();

        const float lgx = lng[j0], lgy = lng[j0 + 1];
        const float lbx = lnb[j0], lby = lnb[j0 + 1];
        const int kc = j0 >> 4, ptig = (j0 >> 1) & 3, hi = (j0 >> 3) & 1;
#pragma unroll
        for (int r = 0; r < 4; r++) {
            int m = m0 + r;
            int bb = m >> 7, u = m & 127;
            float ox = (xs[r] - mu_s[r]) * rs_s[r] * lgx + lbx;
            float oy = (ys[r] - mu_s[r]) * rs_s[r] * lgy + lby;
            __half2 hv = __floats2half2_rn(ox, oy);
            *(__half2*)(g_tlnh + (((size_t)(bb * 32 + kc) * 128 + u) * 16 + ptig * 4 + hi * 2)) = hv;
        }
    } else {
        // ---- B-fragment prep over blocks 128..147 (strided) ----
        for (int idx = (blockIdx.x - 128) * 256 + tid; idx < 12288; idx += 20 * 256) {
            int part = idx >> 12;
            int rem = idx & 4095;
            int kc = rem >> 7;
            int ln2 = (rem >> 2) & 31;
            int wd = idx & 3;
            int nf = part * 2 + (wd >> 1);
            int r = wd & 1;
            int g2 = ln2 >> 2, t2 = ln2 & 3;
            int n = nf * 8 + g2;
            int k0 = kc * 16 + t2 * 2 + r * 8;
            float lo = (n < Vd) ? Wl[k0 * Vd + n] : 0.f;
            float hi = (n < Vd) ? Wl[(k0 + 1) * Vd + n] : 0.f;
            g_Bfrag[idx] = f2h(lo, hi);
        }
        if (blockIdx.x == GRID - 1 && tid < 8 && tid < tailcnt)
            out[tailbase + tid] = (tid < 4) ? (float)slen[tid] : (float)tlen[tid - 4];
    }

    grid_barrier();

    // ============== PHASE 1: quad-tile fused joint ==============
    {
        uint4* Bs = (uint4*)(sm + SM_BS);
        const uint4* Bg = (const uint4*)g_Bfrag;
        for (int i = tid; i < 3072; i += 256) Bs[i] = Bg[i];
        float* bls = (float*)(sm + SM_BLS);
        if (tid < 48) bls[tid] = (tid < Vd) ? bl[tid] : 0.f;
    }

    const uint4* Bsv = (const uint4*)(sm + SM_BS);
    const uint4* srcp4 = (const uint4*)(sm + SM_SRCP);
    const float* bls = (const float*)(sm + SM_BLS);
    const int u0 = w * 16 + gid;

    int par = 0;
    for (int quad = blockIdx.x; quad < NQUADS; quad += gridDim.x) {
        const int tile0 = quad * 4;
        const int b = tile0 >> 9;
        __syncthreads();   // B copy done (first iter) / previous epilogue + srcp reads done

        // stage 4 tiles' src rows as packed half2 (2 uint4 per (kc,tig))
        if (tid < 128) {
            int kc = tid >> 2, tg = tid & 3;
            const float* s0 = src + (size_t)tile0 * Hd + kc * 16 + tg * 2;
            uint4 p01, p23;
            p01.x = f2h(s0[0], s0[1]);
            p01.y = f2h(s0[8], s0[9]);
            p01.z = f2h(s0[Hd + 0], s0[Hd + 1]);
            p01.w = f2h(s0[Hd + 8], s0[Hd + 9]);
            p23.x = f2h(s0[2 * Hd + 0], s0[2 * Hd + 1]);
            p23.y = f2h(s0[2 * Hd + 8], s0[2 * Hd + 9]);
            p23.z = f2h(s0[3 * Hd + 0], s0[3 * Hd + 1]);
            p23.w = f2h(s0[3 * Hd + 8], s0[3 * Hd + 9]);
            ((uint4*)(sm + SM_SRCP))[(par * 128 + tid) * 2] = p01;
            ((uint4*)(sm + SM_SRCP))[(par * 128 + tid) * 2 + 1] = p23;
        }

        // prefetch tln K64-chunks 0,1 (triple-buffered cp.async)
        const char* gtb = (const char*)g_tlnh + (size_t)b * 131072;
#pragma unroll
        for (int pc = 0; pc < 2; ++pc) {
            const char* gp = gtb + pc * 16384 + tid * 64;
            uint32_t sa = smem_u32(sm + SM_TLN + pc * 16384 + tid * 64);
#pragma unroll
            for (int j = 0; j < 4; ++j)
                asm volatile("cp.async.cg.shared.global [%0], [%1], 16;"
                             :: "r"(sa + j * 16), "l"(gp + j * 16) : "memory");
            asm volatile("cp.async.commit_group;" ::: "memory");
        }

        float acc0[6][4], acc1[6][4], acc2[6][4], acc3[6][4];
#pragma unroll
        for (int nf = 0; nf < 6; ++nf)
#pragma unroll
            for (int q = 0; q < 4; ++q) {
                acc0[nf][q] = 0.f; acc1[nf][q] = 0.f;
                acc2[nf][q] = 0.f; acc3[nf][q] = 0.f;
            }

        const int sbase = par * 256;

        for (int c = 0; c < 8; ++c) {
            if (c < 7) asm volatile("cp.async.wait_group 1;" ::: "memory");
            else       asm volatile("cp.async.wait_group 0;" ::: "memory");
            __syncthreads();
            if (c + 2 < 8) {
                int bi = (c + 2) % 3;
                const char* gp = gtb + (c + 2) * 16384 + tid * 64;
                uint32_t sa = smem_u32(sm + SM_TLN + bi * 16384 + tid * 64);
#pragma unroll
                for (int j = 0; j < 4; ++j)
                    asm volatile("cp.async.cg.shared.global [%0], [%1], 16;"
                                 :: "r"(sa + j * 16), "l"(gp + j * 16) : "memory");
                asm volatile("cp.async.commit_group;" ::: "memory");
            }

            const char* tb = sm + SM_TLN + (c % 3) * 16384;
#pragma unroll
            for (int sub = 0; sub < 4; ++sub) {
                const int kc = c * 4 + sub;
                const char* tsub = tb + sub * 4096;
                uint2 A0 = *(const uint2*)(tsub + u0 * 32 + tig * 8);
                uint2 A1 = *(const uint2*)(tsub + (u0 + 8) * 32 + tig * 8);
                uint4 S01 = srcp4[sbase + (kc * 4 + tig) * 2];
                uint4 S23 = srcp4[sbase + (kc * 4 + tig) * 2 + 1];

                const uint4* bp = Bsv + kc * 32 + lane;      // conflict-free LDS.128
                uint4 B0 = bp[0];
                uint4 B1 = bp[1024];
                uint4 B2 = bp[2048];

                // tile 0
                {
                    uint32_t a0 = tanh2(hadd2u(A0.x, S01.x));
                    uint32_t a2 = tanh2(hadd2u(A0.y, S01.y));
                    uint32_t a1 = tanh2(hadd2u(A1.x, S01.x));
                    uint32_t a3 = tanh2(hadd2u(A1.y, S01.y));
                    mma16816(acc0[0], a0, a1, a2, a3, B0.x, B0.y);
                    mma16816(acc0[1], a0, a1, a2, a3, B0.z, B0.w);
                    mma16816(acc0[2], a0, a1, a2, a3, B1.x, B1.y);
                    mma16816(acc0[3], a0, a1, a2, a3, B1.z, B1.w);
                    mma16816(acc0[4], a0, a1, a2, a3, B2.x, B2.y);
                    mma16816(acc0[5], a0, a1, a2, a3, B2.z, B2.w);
                }
                // tile 1
                {
                    uint32_t a0 = tanh2(hadd2u(A0.x, S01.z));
                    uint32_t a2 = tanh2(hadd2u(A0.y, S01.w));
                    uint32_t a1 = tanh2(hadd2u(A1.x, S01.z));
                    uint32_t a3 = tanh2(hadd2u(A1.y, S01.w));
                    mma16816(acc1[0], a0, a1, a2, a3, B0.x, B0.y);
                    mma16816(acc1[1], a0, a1, a2, a3, B0.z, B0.w);
                    mma16816(acc1[2], a0, a1, a2, a3, B1.x, B1.y);
                    mma16816(acc1[3], a0, a1, a2, a3, B1.z, B1.w);
                    mma16816(acc1[4], a0, a1, a2, a3, B2.x, B2.y);
                    mma16816(acc1[5], a0, a1, a2, a3, B2.z, B2.w);
                }
                // tile 2
                {
                    uint32_t a0 = tanh2(hadd2u(A0.x, S23.x));
                    uint32_t a2 = tanh2(hadd2u(A0.y, S23.y));
                    uint32_t a1 = tanh2(hadd2u(A1.x, S23.x));
                    uint32_t a3 = tanh2(hadd2u(A1.y, S23.y));
                    mma16816(acc2[0], a0, a1, a2, a3, B0.x, B0.y);
                    mma16816(acc2[1], a0, a1, a2, a3, B0.z, B0.w);
                    mma16816(acc2[2], a0, a1, a2, a3, B1.x, B1.y);
                    mma16816(acc2[3], a0, a1, a2, a3, B1.z, B1.w);
                    mma16816(acc2[4], a0, a1, a2, a3, B2.x, B2.y);
                    mma16816(acc2[5], a0, a1, a2, a3, B2.z, B2.w);
                }
                // tile 3
                {
                    uint32_t a0 = tanh2(hadd2u(A0.x, S23.z));
                    uint32_t a2 = tanh2(hadd2u(A0.y, S23.w));
                    uint32_t a1 = tanh2(hadd2u(A1.x, S23.z));
                    uint32_t a3 = tanh2(hadd2u(A1.y, S23.w));
                    mma16816(acc3[0], a0, a1, a2, a3, B0.x, B0.y);
                    mma16816(acc3[1], a0, a1, a2, a3, B0.z, B0.w);
                    mma16816(acc3[2], a0, a1, a2, a3, B1.x, B1.y);
                    mma16816(acc3[3], a0, a1, a2, a3, B1.z, B1.w);
                    mma16816(acc3[4], a0, a1, a2, a3, B2.x, B2.y);
                    mma16816(acc3[5], a0, a1, a2, a3, B2.z, B2.w);
                }
            }
        }

        // epilogue: 2 passes of 2 tiles through the 42KB stage
        __syncthreads();   // all warps done reading A chunks
        float* stage = (float*)(sm + SM_TLN);
#pragma unroll
        for (int pass = 0; pass < 2; ++pass) {
            float (*pa)[4] = pass ? acc2 : acc0;
            float (*pb)[4] = pass ? acc3 : acc1;
            float* s00 = stage + u0 * Vd;
            float* s01 = stage + (u0 + 8) * Vd;
            float* s10 = stage + (128 + u0) * Vd;
            float* s11 = stage + (128 + u0 + 8) * Vd;
#pragma unroll
            for (int nf = 0; nf < 6; ++nf) {
                int n = nf * 8 + tig * 2;
                if (n < Vd) {
                    float bb0 = bls[n];
                    s00[n] = pa[nf][0] + bb0;
                    s01[n] = pa[nf][2] + bb0;
                    s10[n] = pb[nf][0] + bb0;
                    s11[n] = pb[nf][2] + bb0;
                }
                if (n + 1 < Vd) {
                    float bb1 = bls[n + 1];
                    s00[n + 1] = pa[nf][1] + bb1;
                    s01[n + 1] = pa[nf][3] + bb1;
                    s10[n + 1] = pb[nf][1] + bb1;
                    s11[n + 1] = pb[nf][3] + bb1;
                }
            }
            __syncthreads();
            {
                float4* dst = (float4*)(out + (size_t)(tile0 + pass * 2) * (Ud * Vd));
                const float4* sg = (const float4*)stage;
                for (int i = tid; i < (2 * Ud * Vd) / 4; i += 256) dst[i] = sg[i];
            }
            __syncthreads();
        }
        par ^= 1;
    }
}

extern "C" void kernel_launch(void* const* d_in, const int* in_sizes, int n_in,
                              void* d_out, int out_size) {
    const float* src = (const float*)d_in[0];
    const int*   slen = (const int*)d_in[1];
    const float* tgt = (const float*)d_in[2];
    const int*   tlen = (const int*)d_in[3];
    const float* W1 = (const float*)d_in[4];
    const float* b1 = (const float*)d_in[5];
    const float* W2 = (const float*)d_in[6];
    const float* b2 = (const float*)d_in[7];
    const float* lng = (const float*)d_in[8];
    const float* lnb = (const float*)d_in[9];
    const float* Wl = (const float*)d_in[10];
    const float* bl = (const float*)d_in[11];
    float* out = (float*)d_out;

    cudaFuncSetAttribute(k_all, cudaFuncAttributeMaxDynamicSharedMemorySize, SM_TOT);

    const long long MAIN = (long long)Bd * Td * Ud * Vd;   // 10,747,904
    int extra = 0;
    if ((long long)out_size > MAIN) {
        extra = (int)((long long)out_size - MAIN);
        if (extra > 8) extra = 8;
    }

    k_all<<<GRID, 256, SM_TOT>>>(src, tgt, W1, b1, W2, b2, lng, lnb, Wl, bl,
                                 out, slen, tlen, MAIN, extra);
}

// round 15
// speedup vs baseline: 1.0612x; 1.0612x over previous
#include <cuda_runtime.h>
#include <cuda_fp16.h>
#include <cstdint>
#include <math.h>

#define Hd 512
#define Bd 4
#define Td 512
#define Ud 128
#define Vd 41
#define NTILES (Bd * Td)
#define NPAIRS (NTILES / 2)
#define GRID 296
#define P0ROWS 16
#define P0BLKS 32

// ---------------- scratch ----------------
__device__ __align__(256) __half g_tlnh[Bd * Ud * Hd];       // LN target fp16, [b][kc(32)][u(128)][perm16]
__device__ __align__(256) uint32_t g_Bfrag[3 * 32 * 32 * 4]; // Wl fp16 B-frags [part(3)][kc][lane][w4]
__device__ unsigned int g_bar = 0;                           // monotonic grid barrier counter

// ---------------- helpers ----------------
__device__ __forceinline__ uint32_t smem_u32(const void* p) {
    uint32_t a;
    asm("{ .reg .u64 t; cvta.to.shared.u64 t, %1; cvt.u32.u64 %0, t; }" : "=r"(a) : "l"(p));
    return a;
}
__device__ __forceinline__ uint32_t f2h(float x, float y) {
    __half2 h = __floats2half2_rn(x, y);
    return *reinterpret_cast<uint32_t*>(&h);
}
__device__ __forceinline__ uint32_t hadd2u(uint32_t a, uint32_t b) {
    uint32_t d;
    asm("add.f16x2 %0, %1, %2;" : "=r"(d) : "r"(a), "r"(b));
    return d;
}
__device__ __forceinline__ uint32_t tanh2(uint32_t x) {
    asm("tanh.approx.f16x2 %0, %0;" : "+r"(x));
    return x;
}
__device__ __forceinline__ void mma16816(float* c, uint32_t a0, uint32_t a1, uint32_t a2, uint32_t a3,
                                         uint32_t b0, uint32_t b1) {
    asm volatile(
        "mma.sync.aligned.m16n8k16.row.col.f32.f16.f16.f32 "
        "{%0,%1,%2,%3}, {%4,%5,%6,%7}, {%8,%9}, {%0,%1,%2,%3};"
        : "+f"(c[0]), "+f"(c[1]), "+f"(c[2]), "+f"(c[3])
        : "r"(a0), "r"(a1), "r"(a2), "r"(a3), "r"(b0), "r"(b1));
}
__device__ __forceinline__ unsigned long long pack2(float x, float y) {
    unsigned long long r; asm("mov.b64 %0, {%1, %2};" : "=l"(r) : "f"(x), "f"(y)); return r;
}
__device__ __forceinline__ void unpack2(unsigned long long v, float& x, float& y) {
    asm("mov.b64 {%0, %1}, %2;" : "=f"(x), "=f"(y) : "l"(v));
}
__device__ __forceinline__ unsigned long long fma2(unsigned long long a, unsigned long long b, unsigned long long c) {
    unsigned long long d; asm("fma.rn.f32x2 %0, %1, %2, %3;" : "=l"(d) : "l"(a), "l"(b), "l"(c)); return d;
}

// replay-safe all-resident grid barrier (monotonic counter, no reset)
__device__ __forceinline__ void grid_barrier() {
    __syncthreads();
    if (threadIdx.x == 0) {
        __threadfence();
        unsigned nb = gridDim.x;
        unsigned t = atomicAdd(&g_bar, 1u);
        unsigned target = (t / nb + 1u) * nb;
        unsigned v;
        do {
            asm volatile("ld.acquire.gpu.global.u32 %0, [%1];" : "=r"(v) : "l"(&g_bar));
        } while (v < target);
    }
    __syncthreads();
}

// ---------------- smem layout ----------------
// phase 0 (16-row target path): As2 64KB + red 1.2KB = 66.7KB  (fits below)
// phase 1: B 48KB | TLN 48KB | SRCP 4KB | BLS 192B = 102.6KB
#define SM_BS   0
#define SM_TLN  49152
#define SM_SRCP 98304
#define SM_BLS  102400
#define SM_TOT  102656     // 2 CTAs x 102656 = 205312 <= 228KB -> 2 CTA/SM, barrier-safe

// =====================================================================
// ONE persistent kernel: phase0 (target path + B prep) -> barrier -> fused
// =====================================================================
__global__ __launch_bounds__(256, 2)
void k_all(const float* __restrict__ src, const float* __restrict__ tgt,
           const float* __restrict__ W1, const float* __restrict__ b1,
           const float* __restrict__ W2, const float* __restrict__ b2,
           const float* __restrict__ lng, const float* __restrict__ lnb,
           const float* __restrict__ Wl, const float* __restrict__ bl,
           float* __restrict__ out,
           const int* __restrict__ slen, const int* __restrict__ tlen,
           long long tailbase, int tailcnt) {
    extern __shared__ __align__(16) char sm[];
    const int tid = threadIdx.x, w = tid >> 5, lane = tid & 31;
    const int gid = lane >> 2, tig = lane & 3;

    // ============== PHASE 0 ==============
    if (blockIdx.x < P0BLKS) {
        // ---- full target path, 16 rows per block (W L2 traffic / 4 vs 128-block split) ----
        unsigned long long (*As2)[Hd] = (unsigned long long(*)[Hd])sm;   // 64KB
        float (*redS)[8] = (float(*)[8])(sm + 65536);
        float (*redQ)[8] = (float(*)[8])(sm + 65536 + 512);
        float* mu_s = (float*)(sm + 65536 + 1024);
        float* rs_s = mu_s + P0ROWS;

        const int m0 = blockIdx.x * P0ROWS;
        for (int i = tid; i < P0ROWS * Hd; i += 256) {
            float v = tgt[m0 * Hd + i];
            ((unsigned long long*)As2)[i] = pack2(v, v);
        }
        __syncthreads();

        const int j0 = tid * 2;
        // GEMM1 + GELU
        unsigned long long acc[P0ROWS];
        {
            unsigned long long bb = pack2(b1[j0], b1[j0 + 1]);
#pragma unroll
            for (int r = 0; r < P0ROWS; r++) acc[r] = bb;
        }
        for (int k = 0; k < Hd; k += 2) {
            unsigned long long wv[2];
#pragma unroll
            for (int q = 0; q < 2; q++) {
                float2 t2 = *(const float2*)(W1 + (k + q) * Hd + j0);
                wv[q] = pack2(t2.x, t2.y);
            }
#pragma unroll
            for (int q = 0; q < 2; q++)
#pragma unroll
                for (int r = 0; r < P0ROWS; r++) acc[r] = fma2(As2[r][k + q], wv[q], acc[r]);
        }
        float gxs[P0ROWS], gys[P0ROWS];
#pragma unroll
        for (int r = 0; r < P0ROWS; r++) {
            float x, y; unpack2(acc[r], x, y);
            gxs[r] = 0.5f * x * (1.0f + erff(x * 0.7071067811865475f));
            gys[r] = 0.5f * y * (1.0f + erff(y * 0.7071067811865475f));
        }
        __syncthreads();          // all As2 reads done
#pragma unroll
        for (int r = 0; r < P0ROWS; r++) {
            As2[r][j0] = pack2(gxs[r], gxs[r]);
            As2[r][j0 + 1] = pack2(gys[r], gys[r]);
        }
        __syncthreads();

        // GEMM2 + LN
        {
            unsigned long long bb = pack2(b2[j0], b2[j0 + 1]);
#pragma unroll
            for (int r = 0; r < P0ROWS; r++) acc[r] = bb;
        }
        for (int k = 0; k < Hd; k += 2) {
            unsigned long long wv[2];
#pragma unroll
            for (int q = 0; q < 2; q++) {
                float2 t2 = *(const float2*)(W2 + (k + q) * Hd + j0);
                wv[q] = pack2(t2.x, t2.y);
            }
#pragma unroll
            for (int q = 0; q < 2; q++)
#pragma unroll
                for (int r = 0; r < P0ROWS; r++) acc[r] = fma2(As2[r][k + q], wv[q], acc[r]);
        }
        float xs[P0ROWS], ys[P0ROWS];
#pragma unroll
        for (int r = 0; r < P0ROWS; r++) unpack2(acc[r], xs[r], ys[r]);

#pragma unroll
        for (int r = 0; r < P0ROWS; r++) {
            float s = xs[r] + ys[r];
            float q = xs[r] * xs[r] + ys[r] * ys[r];
#pragma unroll
            for (int off = 16; off > 0; off >>= 1) {
                s += __shfl_down_sync(0xFFFFFFFFu, s, off);
                q += __shfl_down_sync(0xFFFFFFFFu, q, off);
            }
            if (lane == 0) { redS[r][w] = s; redQ[r][w] = q; }
        }
        __syncthreads();
        if (tid < P0ROWS) {
            float s = 0.f, q = 0.f;
#pragma unroll
            for (int j = 0; j < 8; j++) { s += redS[tid][j]; q += redQ[tid][j]; }
            float mu = s * (1.0f / Hd);
            float var = q * (1.0f / Hd) - mu * mu;
            mu_s[tid] = mu;
            rs_s[tid] = rsqrtf(var + 1e-5f);
        }
        __syncthreads();

        const float lgx = lng[j0], lgy = lng[j0 + 1];
        const float lbx = lnb[j0], lby = lnb[j0 + 1];
        const int kc = j0 >> 4, ptig = (j0 >> 1) & 3, hi = (j0 >> 3) & 1;
#pragma unroll
        for (int r = 0; r < P0ROWS; r++) {
            int m = m0 + r;
            int bb = m >> 7, u = m & 127;
            float ox = (xs[r] - mu_s[r]) * rs_s[r] * lgx + lbx;
            float oy = (ys[r] - mu_s[r]) * rs_s[r] * lgy + lby;
            __half2 hv = __floats2half2_rn(ox, oy);
            *(__half2*)(g_tlnh + (((size_t)(bb * 32 + kc) * 128 + u) * 16 + ptig * 4 + hi * 2)) = hv;
        }
    } else {
        // ---- B-fragment prep over blocks P0BLKS..GRID-1 (strided) ----
        const int nb = GRID - P0BLKS;
        for (int idx = (blockIdx.x - P0BLKS) * 256 + tid; idx < 12288; idx += nb * 256) {
            int part = idx >> 12;
            int rem = idx & 4095;
            int kc = rem >> 7;
            int ln2 = (rem >> 2) & 31;
            int wd = idx & 3;
            int nf = part * 2 + (wd >> 1);
            int r = wd & 1;
            int g2 = ln2 >> 2, t2 = ln2 & 3;
            int n = nf * 8 + g2;
            int k0 = kc * 16 + t2 * 2 + r * 8;
            float lo = (n < Vd) ? Wl[k0 * Vd + n] : 0.f;
            float hi = (n < Vd) ? Wl[(k0 + 1) * Vd + n] : 0.f;
            g_Bfrag[idx] = f2h(lo, hi);
        }
        if (blockIdx.x == GRID - 1 && tid < 8 && tid < tailcnt)
            out[tailbase + tid] = (tid < 4) ? (float)slen[tid] : (float)tlen[tid - 4];
    }

    grid_barrier();

    // ============== PHASE 1: fused joint (R10 structure, unchanged) ==============
    {
        uint4* Bs = (uint4*)(sm + SM_BS);
        const uint4* Bg = (const uint4*)g_Bfrag;
        for (int i = tid; i < 3072; i += 256) Bs[i] = Bg[i];
        float* bls = (float*)(sm + SM_BLS);
        if (tid < 48) bls[tid] = (tid < Vd) ? bl[tid] : 0.f;
    }

    const uint4* Bsv = (const uint4*)(sm + SM_BS);
    const uint4* srcp4 = (const uint4*)(sm + SM_SRCP);
    const float* bls = (const float*)(sm + SM_BLS);
    const int u0 = w * 16 + gid;

    int par = 0;
    for (int pair = blockIdx.x; pair < NPAIRS; pair += gridDim.x) {
        const int tile0 = pair * 2;
        const int b = tile0 >> 9;
        __syncthreads();   // B copy done (first iter) / previous epilogue + srcp reads done

        // stage both tiles' src rows as packed half2 quads
        if (tid < 128) {
            int kc = tid >> 2, tg = tid & 3;
            const float* s0 = src + (size_t)tile0 * Hd + kc * 16 + tg * 2;
            float2 xa0 = *(const float2*)(s0);
            float2 xb0 = *(const float2*)(s0 + 8);
            float2 xa1 = *(const float2*)(s0 + Hd);
            float2 xb1 = *(const float2*)(s0 + Hd + 8);
            uint4 pv;
            pv.x = f2h(xa0.x, xa0.y);
            pv.y = f2h(xb0.x, xb0.y);
            pv.z = f2h(xa1.x, xa1.y);
            pv.w = f2h(xb1.x, xb1.y);
            ((uint4*)(sm + SM_SRCP))[par * 128 + tid] = pv;
        }

        // prefetch tln K64-chunks 0,1 (triple-buffered cp.async)
        const char* gtb = (const char*)g_tlnh + (size_t)b * 131072;
#pragma unroll
        for (int pc = 0; pc < 2; ++pc) {
            const char* gp = gtb + pc * 16384 + tid * 64;
            uint32_t sa = smem_u32(sm + SM_TLN + pc * 16384 + tid * 64);
#pragma unroll
            for (int j = 0; j < 4; ++j)
                asm volatile("cp.async.cg.shared.global [%0], [%1], 16;"
                             :: "r"(sa + j * 16), "l"(gp + j * 16) : "memory");
            asm volatile("cp.async.commit_group;" ::: "memory");
        }

        float acc0[6][4], acc1[6][4];
#pragma unroll
        for (int nf = 0; nf < 6; ++nf)
#pragma unroll
            for (int q = 0; q < 4; ++q) { acc0[nf][q] = 0.f; acc1[nf][q] = 0.f; }

        const int sbase = par * 128;

        for (int c = 0; c < 8; ++c) {
            if (c < 7) asm volatile("cp.async.wait_group 1;" ::: "memory");
            else       asm volatile("cp.async.wait_group 0;" ::: "memory");
            __syncthreads();
            if (c + 2 < 8) {
                int bi = (c + 2) % 3;
                const char* gp = gtb + (c + 2) * 16384 + tid * 64;
                uint32_t sa = smem_u32(sm + SM_TLN + bi * 16384 + tid * 64);
#pragma unroll
                for (int j = 0; j < 4; ++j)
                    asm volatile("cp.async.cg.shared.global [%0], [%1], 16;"
                                 :: "r"(sa + j * 16), "l"(gp + j * 16) : "memory");
                asm volatile("cp.async.commit_group;" ::: "memory");
            }

            const char* tb = sm + SM_TLN + (c % 3) * 16384;
#pragma unroll
            for (int sub = 0; sub < 4; ++sub) {
                const int kc = c * 4 + sub;
                const char* tsub = tb + sub * 4096;
                uint2 A0 = *(const uint2*)(tsub + u0 * 32 + tig * 8);
                uint2 A1 = *(const uint2*)(tsub + (u0 + 8) * 32 + tig * 8);
                uint4 Sv = srcp4[sbase + kc * 4 + tig];      // LDS.128, 4 distinct addrs

                uint32_t a0 = tanh2(hadd2u(A0.x, Sv.x));
                uint32_t a2 = tanh2(hadd2u(A0.y, Sv.y));
                uint32_t a1 = tanh2(hadd2u(A1.x, Sv.x));
                uint32_t a3 = tanh2(hadd2u(A1.y, Sv.y));
                uint32_t c0 = tanh2(hadd2u(A0.x, Sv.z));
                uint32_t c2 = tanh2(hadd2u(A0.y, Sv.w));
                uint32_t c1 = tanh2(hadd2u(A1.x, Sv.z));
                uint32_t c3 = tanh2(hadd2u(A1.y, Sv.w));

                const uint4* bp = Bsv + kc * 32 + lane;      // conflict-free LDS.128
                uint4 B0 = bp[0];
                uint4 B1 = bp[1024];
                uint4 B2 = bp[2048];
                mma16816(acc0[0], a0, a1, a2, a3, B0.x, B0.y);
                mma16816(acc1[0], c0, c1, c2, c3, B0.x, B0.y);
                mma16816(acc0[1], a0, a1, a2, a3, B0.z, B0.w);
                mma16816(acc1[1], c0, c1, c2, c3, B0.z, B0.w);
                mma16816(acc0[2], a0, a1, a2, a3, B1.x, B1.y);
                mma16816(acc1[2], c0, c1, c2, c3, B1.x, B1.y);
                mma16816(acc0[3], a0, a1, a2, a3, B1.z, B1.w);
                mma16816(acc1[3], c0, c1, c2, c3, B1.z, B1.w);
                mma16816(acc0[4], a0, a1, a2, a3, B2.x, B2.y);
                mma16816(acc1[4], c0, c1, c2, c3, B2.x, B2.y);
                mma16816(acc0[5], a0, a1, a2, a3, B2.z, B2.w);
                mma16816(acc1[5], c0, c1, c2, c3, B2.z, B2.w);
            }
        }

        // epilogue: stage both tiles (42KB in tln area), then coalesced stores
        __syncthreads();   // all warps done reading A chunks
        float* stage = (float*)(sm + SM_TLN);
        {
            float* s00 = stage + u0 * Vd;
            float* s01 = stage + (u0 + 8) * Vd;
            float* s10 = stage + (128 + u0) * Vd;
            float* s11 = stage + (128 + u0 + 8) * Vd;
#pragma unroll
            for (int nf = 0; nf < 6; ++nf) {
                int n = nf * 8 + tig * 2;
                if (n < Vd) {
                    float bb0 = bls[n];
                    s00[n] = acc0[nf][0] + bb0;
                    s01[n] = acc0[nf][2] + bb0;
                    s10[n] = acc1[nf][0] + bb0;
                    s11[n] = acc1[nf][2] + bb0;
                }
                if (n + 1 < Vd) {
                    float bb1 = bls[n + 1];
                    s00[n + 1] = acc0[nf][1] + bb1;
                    s01[n + 1] = acc0[nf][3] + bb1;
                    s10[n + 1] = acc1[nf][1] + bb1;
                    s11[n + 1] = acc1[nf][3] + bb1;
                }
            }
        }
        __syncthreads();
        {
            float4* dst = (float4*)(out + (size_t)tile0 * (Ud * Vd));
            const float4* sg = (const float4*)stage;
            for (int i = tid; i < (2 * Ud * Vd) / 4; i += 256) dst[i] = sg[i];
        }
        par ^= 1;
    }
}

extern "C" void kernel_launch(void* const* d_in, const int* in_sizes, int n_in,
                              void* d_out, int out_size) {
    const float* src = (const float*)d_in[0];
    const int*   slen = (const int*)d_in[1];
    const float* tgt = (const float*)d_in[2];
    const int*   tlen = (const int*)d_in[3];
    const float* W1 = (const float*)d_in[4];
    const float* b1 = (const float*)d_in[5];
    const float* W2 = (const float*)d_in[6];
    const float* b2 = (const float*)d_in[7];
    const float* lng = (const float*)d_in[8];
    const float* lnb = (const float*)d_in[9];
    const float* Wl = (const float*)d_in[10];
    const float* bl = (const float*)d_in[11];
    float* out = (float*)d_out;

    cudaFuncSetAttribute(k_all, cudaFuncAttributeMaxDynamicSharedMemorySize, SM_TOT);

    const long long MAIN = (long long)Bd * Td * Ud * Vd;   // 10,747,904
    int extra = 0;
    if ((long long)out_size > MAIN) {
        extra = (int)((long long)out_size - MAIN);
        if (extra > 8) extra = 8;
    }

    k_all<<<GRID, 256, SM_TOT>>>(src, tgt, W1, b1, W2, b2, lng, lnb, Wl, bl,
                                 out, slen, tlen, MAIN, extra);
}

// round 17
// speedup vs baseline: 1.8760x; 1.7678x over previous
#include <cuda_runtime.h>
#include <cuda_fp16.h>
#include <cstdint>
#include <math.h>

#define Hd 512
#define Bd 4
#define Td 512
#define Ud 128
#define Vd 41
#define NTILES (Bd * Td)
#define NPAIRS (NTILES / 2)
#define GRID 296

// ---------------- scratch ----------------
__device__ __align__(256) __half g_tlnh[Bd * Ud * Hd];       // LN target fp16, [b][kc(32)][u(128)][perm16]
__device__ __align__(256) uint32_t g_Bfrag[3 * 32 * 32 * 4]; // Wl fp16 B-frags [part(3)][kc][lane][w4]
__device__ unsigned int g_bar = 0;                           // monotonic grid barrier counter

// ---------------- helpers ----------------
__device__ __forceinline__ uint32_t smem_u32(const void* p) {
    uint32_t a;
    asm("{ .reg .u64 t; cvta.to.shared.u64 t, %1; cvt.u32.u64 %0, t; }" : "=r"(a) : "l"(p));
    return a;
}
__device__ __forceinline__ uint32_t f2h(float x, float y) {
    __half2 h = __floats2half2_rn(x, y);
    return *reinterpret_cast<uint32_t*>(&h);
}
__device__ __forceinline__ uint32_t hadd2u(uint32_t a, uint32_t b) {
    uint32_t d;
    asm("add.f16x2 %0, %1, %2;" : "=r"(d) : "r"(a), "r"(b));
    return d;
}
__device__ __forceinline__ uint32_t tanh2(uint32_t x) {
    asm("tanh.approx.f16x2 %0, %0;" : "+r"(x));
    return x;
}
__device__ __forceinline__ void mma16816(float* c, uint32_t a0, uint32_t a1, uint32_t a2, uint32_t a3,
                                         uint32_t b0, uint32_t b1) {
    asm volatile(
        "mma.sync.aligned.m16n8k16.row.col.f32.f16.f16.f32 "
        "{%0,%1,%2,%3}, {%4,%5,%6,%7}, {%8,%9}, {%0,%1,%2,%3};"
        : "+f"(c[0]), "+f"(c[1]), "+f"(c[2]), "+f"(c[3])
        : "r"(a0), "r"(a1), "r"(a2), "r"(a3), "r"(b0), "r"(b1));
}
__device__ __forceinline__ unsigned long long pack2(float x, float y) {
    unsigned long long r; asm("mov.b64 %0, {%1, %2};" : "=l"(r) : "f"(x), "f"(y)); return r;
}
__device__ __forceinline__ void unpack2(unsigned long long v, float& x, float& y) {
    asm("mov.b64 {%0, %1}, %2;" : "=f"(x), "=f"(y) : "l"(v));
}
__device__ __forceinline__ unsigned long long fma2(unsigned long long a, unsigned long long b, unsigned long long c) {
    unsigned long long d; asm("fma.rn.f32x2 %0, %1, %2, %3;" : "=l"(d) : "l"(a), "l"(b), "l"(c)); return d;
}

// replay-safe all-resident grid barrier (monotonic counter, no reset)
__device__ __forceinline__ void grid_barrier() {
    __syncthreads();
    if (threadIdx.x == 0) {
        __threadfence();
        unsigned nb = gridDim.x;
        unsigned t = atomicAdd(&g_bar, 1u);
        unsigned target = (t / nb + 1u) * nb;
        unsigned v;
        do {
            asm volatile("ld.acquire.gpu.global.u32 %0, [%1];" : "=r"(v) : "l"(&g_bar));
        } while (v < target);
    }
    __syncthreads();
}

// ---------------- smem layout (phase 1) ----------------
#define SM_BS   0          // 48KB B frags (3 conflict-free 16KB arrays)
#define SM_AB   49152      // 48KB warp-private A buffers: warp w at +w*6144, 3 chunks x 2KB
                           // (reused as 42KB epilogue stage)
#define SM_SRCP 98304      // 2 par x 128 x uint4 = 4KB
#define SM_BLS  102400     // 192B padded bias
#define SM_TOT  102656     // 2 CTAs x 102656 = 205312 <= 228KB -> 2 CTA/SM

// =====================================================================
// ONE persistent kernel: phase0 (R10 config) -> barrier -> barrier-free fused
// =====================================================================
__global__ __launch_bounds__(256, 2)
void k_all(const float* __restrict__ src, const float* __restrict__ tgt,
           const float* __restrict__ W1, const float* __restrict__ b1,
           const float* __restrict__ W2, const float* __restrict__ b2,
           const float* __restrict__ lng, const float* __restrict__ lnb,
           const float* __restrict__ Wl, const float* __restrict__ bl,
           float* __restrict__ out,
           const int* __restrict__ slen, const int* __restrict__ tlen,
           long long tailbase, int tailcnt) {
    extern __shared__ __align__(16) char sm[];
    const int tid = threadIdx.x, w = tid >> 5, lane = tid & 31;
    const int gid = lane >> 2, tig = lane & 3;

    // ============== PHASE 0 (exact R10 config: 128 blocks x 4 rows) ==============
    if (blockIdx.x < 128) {
        unsigned long long (*As2)[Hd] = (unsigned long long(*)[Hd])sm;   // 16KB
        float (*redS)[8] = (float(*)[8])(sm + 16384);
        float (*redQ)[8] = (float(*)[8])(sm + 16384 + 128);
        float* mu_s = (float*)(sm + 16384 + 256);
        float* rs_s = mu_s + 4;

        const int m0 = blockIdx.x * 4;
        for (int i = tid; i < 4 * Hd; i += 256) {
            float v = tgt[m0 * Hd + i];
            ((unsigned long long*)As2)[i] = pack2(v, v);
        }
        __syncthreads();

        const int j0 = tid * 2;
        unsigned long long acc[4];
        {
            unsigned long long bb = pack2(b1[j0], b1[j0 + 1]);
#pragma unroll
            for (int r = 0; r < 4; r++) acc[r] = bb;
        }
        for (int k = 0; k < Hd; k += 4) {
            unsigned long long wv[4];
#pragma unroll
            for (int q = 0; q < 4; q++) {
                float2 t2 = *(const float2*)(W1 + (k + q) * Hd + j0);
                wv[q] = pack2(t2.x, t2.y);
            }
#pragma unroll
            for (int q = 0; q < 4; q++)
#pragma unroll
                for (int r = 0; r < 4; r++) acc[r] = fma2(As2[r][k + q], wv[q], acc[r]);
        }
        float gxs[4], gys[4];
#pragma unroll
        for (int r = 0; r < 4; r++) {
            float x, y; unpack2(acc[r], x, y);
            gxs[r] = 0.5f * x * (1.0f + erff(x * 0.7071067811865475f));
            gys[r] = 0.5f * y * (1.0f + erff(y * 0.7071067811865475f));
        }
        __syncthreads();
#pragma unroll
        for (int r = 0; r < 4; r++) {
            As2[r][j0] = pack2(gxs[r], gxs[r]);
            As2[r][j0 + 1] = pack2(gys[r], gys[r]);
        }
        __syncthreads();

        {
            unsigned long long bb = pack2(b2[j0], b2[j0 + 1]);
#pragma unroll
            for (int r = 0; r < 4; r++) acc[r] = bb;
        }
        for (int k = 0; k < Hd; k += 4) {
            unsigned long long wv[4];
#pragma unroll
            for (int q = 0; q < 4; q++) {
                float2 t2 = *(const float2*)(W2 + (k + q) * Hd + j0);
                wv[q] = pack2(t2.x, t2.y);
            }
#pragma unroll
            for (int q = 0; q < 4; q++)
#pragma unroll
                for (int r = 0; r < 4; r++) acc[r] = fma2(As2[r][k + q], wv[q], acc[r]);
        }
        float xs[4], ys[4];
#pragma unroll
        for (int r = 0; r < 4; r++) unpack2(acc[r], xs[r], ys[r]);

#pragma unroll
        for (int r = 0; r < 4; r++) {
            float s = xs[r] + ys[r];
            float q = xs[r] * xs[r] + ys[r] * ys[r];
#pragma unroll
            for (int off = 16; off > 0; off >>= 1) {
                s += __shfl_down_sync(0xFFFFFFFFu, s, off);
                q += __shfl_down_sync(0xFFFFFFFFu, q, off);
            }
            if (lane == 0) { redS[r][w] = s; redQ[r][w] = q; }
        }
        __syncthreads();
        if (tid < 4) {
            float s = 0.f, q = 0.f;
#pragma unroll
            for (int j = 0; j < 8; j++) { s += redS[tid][j]; q += redQ[tid][j]; }
            float mu = s * (1.0f / Hd);
            float var = q * (1.0f / Hd) - mu * mu;
            mu_s[tid] = mu;
            rs_s[tid] = rsqrtf(var + 1e-5f);
        }
        __syncthreads();

        const float lgx = lng[j0], lgy = lng[j0 + 1];
        const float lbx = lnb[j0], lby = lnb[j0 + 1];
        const int kc = j0 >> 4, ptig = (j0 >> 1) & 3, hi = (j0 >> 3) & 1;
#pragma unroll
        for (int r = 0; r < 4; r++) {
            int m = m0 + r;
            int bb = m >> 7, u = m & 127;
            float ox = (xs[r] - mu_s[r]) * rs_s[r] * lgx + lbx;
            float oy = (ys[r] - mu_s[r]) * rs_s[r] * lgy + lby;
            __half2 hv = __floats2half2_rn(ox, oy);
            *(__half2*)(g_tlnh + (((size_t)(bb * 32 + kc) * 128 + u) * 16 + ptig * 4 + hi * 2)) = hv;
        }
    } else if (blockIdx.x < 176) {
        // ---- B-fragment prep (48 slices) ----
        int idx = (blockIdx.x - 128) * 256 + tid;   // 0..12287
        int part = idx >> 12;
        int rem = idx & 4095;
        int kc = rem >> 7;
        int ln2 = (rem >> 2) & 31;
        int wd = idx & 3;
        int nf = part * 2 + (wd >> 1);
        int r = wd & 1;
        int g2 = ln2 >> 2, t2 = ln2 & 3;
        int n = nf * 8 + g2;
        int k0 = kc * 16 + t2 * 2 + r * 8;
        float lo = (n < Vd) ? Wl[k0 * Vd + n] : 0.f;
        float hi = (n < Vd) ? Wl[(k0 + 1) * Vd + n] : 0.f;
        g_Bfrag[idx] = f2h(lo, hi);
    } else if (blockIdx.x == GRID - 1) {
        if (tid < 8 && tid < tailcnt)
            out[tailbase + tid] = (tid < 4) ? (float)slen[tid] : (float)tlen[tid - 4];
    }

    grid_barrier();

    // ============== PHASE 1: fused joint, barrier-free k-loop ==============
    {
        uint4* Bs = (uint4*)(sm + SM_BS);
        const uint4* Bg = (const uint4*)g_Bfrag;
        for (int i = tid; i < 3072; i += 256) Bs[i] = Bg[i];
        float* bls = (float*)(sm + SM_BLS);
        if (tid < 48) bls[tid] = (tid < Vd) ? bl[tid] : 0.f;
    }

    const uint4* Bsv = (const uint4*)(sm + SM_BS);
    const uint4* srcp4 = (const uint4*)(sm + SM_SRCP);
    const float* bls = (const float*)(sm + SM_BLS);
    const int u0 = w * 16 + gid;
    char* const abuf = sm + SM_AB + w * 6144;              // warp-private A buffers (3 x 2KB)
    const uint32_t abufa = smem_u32(abuf);

    int par = 0;
    for (int pair = blockIdx.x; pair < NPAIRS; pair += gridDim.x) {
        const int tile0 = pair * 2;
        const int b = tile0 >> 9;
        __syncthreads();   // B/bls staged (first iter); prev epilogue STG + srcp reads done

        // stage both tiles' src rows as packed half2 quads
        if (tid < 128) {
            int kc = tid >> 2, tg = tid & 3;
            const float* s0 = src + (size_t)tile0 * Hd + kc * 16 + tg * 2;
            float2 xa0 = *(const float2*)(s0);
            float2 xb0 = *(const float2*)(s0 + 8);
            float2 xa1 = *(const float2*)(s0 + Hd);
            float2 xb1 = *(const float2*)(s0 + Hd + 8);
            uint4 pv;
            pv.x = f2h(xa0.x, xa0.y);
            pv.y = f2h(xb0.x, xb0.y);
            pv.z = f2h(xa1.x, xa1.y);
            pv.w = f2h(xb1.x, xb1.y);
            ((uint4*)(sm + SM_SRCP))[par * 128 + tid] = pv;
        }

        // warp-private prefetch of A chunks 0,1 (each chunk: 4 kc x 512B of this warp's u-rows)
        const char* gtb = (const char*)g_tlnh + (size_t)b * 131072 + (size_t)w * 512 + lane * 16;
#pragma unroll
        for (int pc = 0; pc < 2; ++pc) {
            const char* gp = gtb + pc * 16384;
            uint32_t sa = abufa + pc * 2048 + lane * 16;
#pragma unroll
            for (int s2 = 0; s2 < 4; ++s2)
                asm volatile("cp.async.cg.shared.global [%0], [%1], 16;"
                             :: "r"(sa + s2 * 512), "l"(gp + s2 * 4096) : "memory");
            asm volatile("cp.async.commit_group;" ::: "memory");
        }

        float acc0[6][4], acc1[6][4];
#pragma unroll
        for (int nf = 0; nf < 6; ++nf)
#pragma unroll
            for (int q = 0; q < 4; ++q) { acc0[nf][q] = 0.f; acc1[nf][q] = 0.f; }

        const int sbase = par * 128;
        __syncthreads();   // srcp staged and visible to all warps

        for (int c = 0; c < 8; ++c) {
            if (c < 7) asm volatile("cp.async.wait_group 1;" ::: "memory");
            else       asm volatile("cp.async.wait_group 0;" ::: "memory");
            __syncwarp();
            if (c + 2 < 8) {
                int bi = (c + 2) % 3;
                const char* gp = gtb + (c + 2) * 16384;
                uint32_t sa = abufa + bi * 2048 + lane * 16;
#pragma unroll
                for (int s2 = 0; s2 < 4; ++s2)
                    asm volatile("cp.async.cg.shared.global [%0], [%1], 16;"
                                 :: "r"(sa + s2 * 512), "l"(gp + s2 * 4096) : "memory");
                asm volatile("cp.async.commit_group;" ::: "memory");
            }

            const char* tb = abuf + (c % 3) * 2048;
#pragma unroll
            for (int sub = 0; sub < 4; ++sub) {
                const int kc = c * 4 + sub;
                const char* tsub = tb + sub * 512;
                uint2 A0 = *(const uint2*)(tsub + gid * 32 + tig * 8);
                uint2 A1 = *(const uint2*)(tsub + (gid + 8) * 32 + tig * 8);
                uint4 Sv = srcp4[sbase + kc * 4 + tig];      // LDS.128 broadcast

                uint32_t a0 = tanh2(hadd2u(A0.x, Sv.x));
                uint32_t a2 = tanh2(hadd2u(A0.y, Sv.y));
                uint32_t a1 = tanh2(hadd2u(A1.x, Sv.x));
                uint32_t a3 = tanh2(hadd2u(A1.y, Sv.y));
                uint32_t c0 = tanh2(hadd2u(A0.x, Sv.z));
                uint32_t c2 = tanh2(hadd2u(A0.y, Sv.w));
                uint32_t c1 = tanh2(hadd2u(A1.x, Sv.z));
                uint32_t c3 = tanh2(hadd2u(A1.y, Sv.w));

                const uint4* bp = Bsv + kc * 32 + lane;      // conflict-free LDS.128
                uint4 B0 = bp[0];
                uint4 B1 = bp[1024];
                uint4 B2 = bp[2048];
                mma16816(acc0[0], a0, a1, a2, a3, B0.x, B0.y);
                mma16816(acc1[0], c0, c1, c2, c3, B0.x, B0.y);
                mma16816(acc0[1], a0, a1, a2, a3, B0.z, B0.w);
                mma16816(acc1[1], c0, c1, c2, c3, B0.z, B0.w);
                mma16816(acc0[2], a0, a1, a2, a3, B1.x, B1.y);
                mma16816(acc1[2], c0, c1, c2, c3, B1.x, B1.y);
                mma16816(acc0[3], a0, a1, a2, a3, B1.z, B1.w);
                mma16816(acc1[3], c0, c1, c2, c3, B1.z, B1.w);
                mma16816(acc0[4], a0, a1, a2, a3, B2.x, B2.y);
                mma16816(acc1[4], c0, c1, c2, c3, B2.x, B2.y);
                mma16816(acc0[5], a0, a1, a2, a3, B2.z, B2.w);
                mma16816(acc1[5], c0, c1, c2, c3, B2.z, B2.w);
            }
        }

        // epilogue: stage both tiles in A-buffer area (all warps done with A bufs)
        __syncthreads();
        float* stage = (float*)(sm + SM_AB);
        {
            float* s00 = stage + u0 * Vd;
            float* s01 = stage + (u0 + 8) * Vd;
            float* s10 = stage + (128 + u0) * Vd;
            float* s11 = stage + (128 + u0 + 8) * Vd;
#pragma unroll
            for (int nf = 0; nf < 6; ++nf) {
                int n = nf * 8 + tig * 2;
                if (n < Vd) {
                    float bb0 = bls[n];
                    s00[n] = acc0[nf][0] + bb0;
                    s01[n] = acc0[nf][2] + bb0;
                    s10[n] = acc1[nf][0] + bb0;
                    s11[n] = acc1[nf][2] + bb0;
                }
                if (n + 1 < Vd) {
                    float bb1 = bls[n + 1];
                    s00[n + 1] = acc0[nf][1] + bb1;
                    s01[n + 1] = acc0[nf][3] + bb1;
                    s10[n + 1] = acc1[nf][1] + bb1;
                    s11[n + 1] = acc1[nf][3] + bb1;
                }
            }
        }
        __syncthreads();
        {
            float4* dst = (float4*)(out + (size_t)tile0 * (Ud * Vd));
            const float4* sg = (const float4*)stage;
            for (int i = tid; i < (2 * Ud * Vd) / 4; i += 256) dst[i] = sg[i];
        }
        par ^= 1;
    }
}

extern "C" void kernel_launch(void* const* d_in, const int* in_sizes, int n_in,
                              void* d_out, int out_size) {
    const float* src = (const float*)d_in[0];
    const int*   slen = (const int*)d_in[1];
    const float* tgt = (const float*)d_in[2];
    const int*   tlen = (const int*)d_in[3];
    const float* W1 = (const float*)d_in[4];
    const float* b1 = (const float*)d_in[5];
    const float* W2 = (const float*)d_in[6];
    const float* b2 = (const float*)d_in[7];
    const float* lng = (const float*)d_in[8];
    const float* lnb = (const float*)d_in[9];
    const float* Wl = (const float*)d_in[10];
    const float* bl = (const float*)d_in[11];
    float* out = (float*)d_out;

    cudaFuncSetAttribute(k_all, cudaFuncAttributeMaxDynamicSharedMemorySize, SM_TOT);

    const long long MAIN = (long long)Bd * Td * Ud * Vd;   // 10,747,904
    int extra = 0;
    if ((long long)out_size > MAIN) {
        extra = (int)((long long)out_size - MAIN);
        if (extra > 8) extra = 8;
    }

    k_all<<<GRID, 256, SM_TOT>>>(src, tgt, W1, b1, W2, b2, lng, lnb, Wl, bl,
                                 out, slen, tlen, MAIN, extra);
}